// round 10
// baseline (speedup 1.0000x reference)
#include <cuda_runtime.h>
#include <cuda_fp16.h>
#include <cuda_bf16.h>
#include <stdint.h>

// Problem shape (fixed by the reference)
#define BATCH 4
#define SEQ   2048
#define EMB   1024

// ---------------- scratch (device globals; no cudaMalloc allowed) ----------
__device__ __half d_Qh[(size_t)BATCH * SEQ * EMB];           // 16 MB (Q * 1/32)
__device__ __half d_Kh[(size_t)BATCH * SEQ * EMB];           // 16 MB
__device__ __half d_Vt[(size_t)BATCH * SEQ * EMB];           // 16 MB (V^T: [B][E][S])
__device__ __half d_Sh[(size_t)BATCH * SEQ * SEQ];           // 32 MB (scores fp16)
__device__ __half d_P [(size_t)BATCH * SEQ * SEQ];           // 32 MB (softmax probs fp16)

// ---------------- fused Q/K fp32 -> fp16 convert ----------------------------
__global__ void cvt_qk(const float* __restrict__ Q, const float* __restrict__ K,
                       __half* __restrict__ Qh, __half* __restrict__ Kh, long n)
{
    const float* in  = blockIdx.y ? K : Q;
    __half*      out = blockIdx.y ? Kh : Qh;
    float scale      = blockIdx.y ? 1.0f : 0.03125f;   // 1/sqrt(1024) folded into Q
    long i = (long)blockIdx.x * blockDim.x + threadIdx.x;
    long stride = (long)gridDim.x * blockDim.x;
    for (long idx = i * 4; idx < n; idx += stride * 4) {
        float4 v = *reinterpret_cast<const float4*>(in + idx);
        __half2 h0 = __floats2half2_rn(v.x * scale, v.y * scale);
        __half2 h1 = __floats2half2_rn(v.z * scale, v.w * scale);
        *reinterpret_cast<__half2*>(out + idx)     = h0;
        *reinterpret_cast<__half2*>(out + idx + 2) = h1;
    }
}

// ---------------- V transpose + convert: V[B][S][E] -> Vt[B][E][S] ---------
__global__ void transpose_v(const float* __restrict__ V, __half* __restrict__ Vt)
{
    __shared__ float tile[32][33];
    int b  = blockIdx.z;
    int e0 = blockIdx.x * 32;
    int j0 = blockIdx.y * 32;
    const float* Vb  = V  + (size_t)b * SEQ * EMB;
    __half*      Vtb = Vt + (size_t)b * SEQ * EMB;
    for (int r = threadIdx.y; r < 32; r += 8)
        tile[r][threadIdx.x] = Vb[(size_t)(j0 + r) * EMB + e0 + threadIdx.x];
    __syncthreads();
    for (int r = threadIdx.y; r < 32; r += 8)
        Vtb[(size_t)(e0 + r) * SEQ + j0 + threadIdx.x] = __float2half_rn(tile[threadIdx.x][r]);
}

// ---------------- helpers ---------------------------------------------------
__device__ __forceinline__ uint32_t smem_u32(const void* p)
{
    uint32_t a;
    asm("{ .reg .u64 t; cvta.to.shared.u64 t, %1; cvt.u32.u64 %0, t; }" : "=r"(a) : "l"(p));
    return a;
}

__device__ __forceinline__ void cp_async16(uint32_t dst, const void* src)
{
    asm volatile("cp.async.cg.shared.global [%0], [%1], 16;" :: "r"(dst), "l"(src));
}
#define CP_COMMIT() asm volatile("cp.async.commit_group;" ::: "memory")
#define CP_WAIT(n)  asm volatile("cp.async.wait_group %0;" :: "n"(n) : "memory")

__device__ __forceinline__ void ldsm_x4_u(uint32_t& r0, uint32_t& r1, uint32_t& r2, uint32_t& r3,
                                          uint32_t sa)
{
    asm volatile("ldmatrix.sync.aligned.m8n8.x4.shared.b16 {%0,%1,%2,%3}, [%4];"
                 : "=r"(r0), "=r"(r1), "=r"(r2), "=r"(r3) : "r"(sa));
}

__device__ __forceinline__ void mma16816(float* d, const uint32_t* a, const uint32_t* b)
{
    asm("mma.sync.aligned.m16n8k16.row.col.f32.f16.f16.f32 "
        "{%0,%1,%2,%3}, {%4,%5,%6,%7}, {%8,%9}, {%0,%1,%2,%3};"
        : "+f"(d[0]), "+f"(d[1]), "+f"(d[2]), "+f"(d[3])
        : "r"(a[0]), "r"(a[1]), "r"(a[2]), "r"(a[3]), "r"(b[0]), "r"(b[1]));
}

// ---------------- GEMM: 128x128 tile, BK=64, 3-stage cp.async ring ----------
// Row pitch 72 halfs = 144 B (16B-aligned, conflict-free ldmatrix as in R2/R9).
// 3 stages -> the load target at iter c is stage (c-1)%3, already fully read
// before the top-of-iteration barrier => ONE __syncthreads per chunk.
#define BM 128
#define BN 128
#define BKT 64
#define ROWB   144                       // bytes per smem row
#define ABYT   (BM * ROWB)               // 18432
#define STGB   (2 * ABYT)                // 36864 per stage (A + B)
#define GEMM_DSMEM (3 * STGB)            // 110592

// issue cp.async for chunk c of both tiles into stage s
#define CPLOAD(Ab, Bb, Kdim, c, s)                                                        \
    {                                                                                     \
        uint32_t so = (uint32_t)((s) * STGB);                                             \
        const __half* a0 = (Ab) + (size_t)(tm + (tid >> 3)) * (Kdim) + (c) * BKT + (tid & 7) * 8; \
        const __half* b0 = (Bb) + (size_t)(tn + (tid >> 3)) * (Kdim) + (c) * BKT + (tid & 7) * 8; \
        uint32_t d0 = sbase + so + (uint32_t)((tid >> 3) * ROWB + (tid & 7) * 16);        \
        _Pragma("unroll")                                                                 \
        for (int r = 0; r < 4; ++r) {                                                     \
            cp_async16(d0 + (uint32_t)(r * 32 * ROWB),        a0 + (size_t)(r * 32) * (Kdim)); \
            cp_async16(d0 + ABYT + (uint32_t)(r * 32 * ROWB), b0 + (size_t)(r * 32) * (Kdim)); \
        }                                                                                 \
    }

// 3-stage mainloop, single barrier per chunk
#define GEMM_MAINLOOP(Ab, Bb, Kdim)                                                       \
    {                                                                                     \
        const int NC = (Kdim) / BKT;                                                      \
        CPLOAD(Ab, Bb, Kdim, 0, 0) CP_COMMIT();                                           \
        CPLOAD(Ab, Bb, Kdim, 1, 1) CP_COMMIT();                                           \
        for (int c = 0; c < NC; ++c) {                                                    \
            if (c + 1 < NC) { CP_WAIT(1); } else { CP_WAIT(0); }                          \
            __syncthreads();                                                              \
            if (c + 2 < NC) { CPLOAD(Ab, Bb, Kdim, c + 2, (c + 2) % 3) CP_COMMIT(); }     \
            const uint32_t so = (uint32_t)((c % 3) * STGB);                               \
            _Pragma("unroll")                                                             \
            for (int kk = 0; kk < BKT; kk += 16) {                                        \
                uint32_t af[4][4];                                                        \
                uint32_t bf[4][2];                                                        \
                _Pragma("unroll")                                                         \
                for (int mt = 0; mt < 4; ++mt)                                            \
                    ldsm_x4_u(af[mt][0], af[mt][1], af[mt][2], af[mt][3],                 \
                              sbase + so + (uint32_t)((wm + mt * 16 + (lane & 15)) * ROWB \
                                                      + (kk + ((lane >> 4) << 3)) * 2));  \
                _Pragma("unroll")                                                         \
                for (int nb = 0; nb < 2; ++nb) {                                          \
                    uint32_t r0, r1, r2, r3;                                              \
                    ldsm_x4_u(r0, r1, r2, r3,                                             \
                              sbase + so + ABYT + (uint32_t)((wn + nb * 16 + (lane & 15)) * ROWB \
                                                      + (kk + ((lane >> 4) << 3)) * 2));  \
                    bf[nb * 2 + 0][0] = r0; bf[nb * 2 + 0][1] = r2;                       \
                    bf[nb * 2 + 1][0] = r1; bf[nb * 2 + 1][1] = r3;                       \
                }                                                                         \
                _Pragma("unroll")                                                         \
                for (int mt = 0; mt < 4; ++mt)                                            \
                    _Pragma("unroll")                                                     \
                    for (int nt = 0; nt < 4; ++nt)                                        \
                        mma16816(acc[mt][nt], af[mt], bf[nt]);                            \
            }                                                                             \
        }                                                                                 \
    }

// ---------------- GEMM1: S = (Qs) @ K^T, fp32 acc, fp16 out -----------------
__global__ void __launch_bounds__(256)
gemm_s(const __half* __restrict__ A, const __half* __restrict__ B,
       __half* __restrict__ S)
{
    extern __shared__ char dsm[];
    const uint32_t sbase = smem_u32(dsm);

    const int b = blockIdx.z;
    const __half* Ab = A + (size_t)b * SEQ * EMB;
    const __half* Bb = B + (size_t)b * SEQ * EMB;
    __half*       Sb = S + (size_t)b * SEQ * SEQ;

    const int tm = blockIdx.y * BM;
    const int tn = blockIdx.x * BN;
    const int tid  = threadIdx.x;
    const int wid  = tid >> 5;
    const int lane = tid & 31;
    const int wm = (wid & 1) * 64;
    const int wn = (wid >> 1) * 32;

    float acc[4][4][4];
#pragma unroll
    for (int i = 0; i < 4; i++)
#pragma unroll
        for (int j = 0; j < 4; j++)
#pragma unroll
            for (int k = 0; k < 4; k++) acc[i][j][k] = 0.f;

    GEMM_MAINLOOP(Ab, Bb, EMB)

#pragma unroll
    for (int mt = 0; mt < 4; ++mt) {
#pragma unroll
        for (int nt = 0; nt < 4; ++nt) {
            int r = tm + wm + mt * 16 + (lane >> 2);
            int c = tn + wn + nt * 8 + ((lane & 3) << 1);
            *reinterpret_cast<__half2*>(&Sb[(size_t)r * SEQ + c]) =
                __floats2half2_rn(acc[mt][nt][0], acc[mt][nt][1]);
            *reinterpret_cast<__half2*>(&Sb[(size_t)(r + 8) * SEQ + c]) =
                __floats2half2_rn(acc[mt][nt][2], acc[mt][nt][3]);
        }
    }
}

// ---------------- GEMM2: O = P @ Vt^T, fp32 acc, fp32 out -------------------
__global__ void __launch_bounds__(256)
gemm_o(const __half* __restrict__ A, const __half* __restrict__ B,
       float* __restrict__ C)
{
    extern __shared__ char dsm[];
    const uint32_t sbase = smem_u32(dsm);

    const int b = blockIdx.z;
    const __half* Ab = A + (size_t)b * SEQ * SEQ;   // P: K = SEQ
    const __half* Bb = B + (size_t)b * SEQ * EMB;   // Vt: K = SEQ
    float*        Cb = C + (size_t)b * SEQ * EMB;

    const int tm = blockIdx.y * BM;
    const int tn = blockIdx.x * BN;
    const int tid  = threadIdx.x;
    const int wid  = tid >> 5;
    const int lane = tid & 31;
    const int wm = (wid & 1) * 64;
    const int wn = (wid >> 1) * 32;

    float acc[4][4][4];
#pragma unroll
    for (int i = 0; i < 4; i++)
#pragma unroll
        for (int j = 0; j < 4; j++)
#pragma unroll
            for (int k = 0; k < 4; k++) acc[i][j][k] = 0.f;

    GEMM_MAINLOOP(Ab, Bb, SEQ)

#pragma unroll
    for (int mt = 0; mt < 4; ++mt) {
#pragma unroll
        for (int nt = 0; nt < 4; ++nt) {
            int r = tm + wm + mt * 16 + (lane >> 2);
            int c = tn + wn + nt * 8 + ((lane & 3) << 1);
            *reinterpret_cast<float2*>(&Cb[(size_t)r * EMB + c]) =
                make_float2(acc[mt][nt][0], acc[mt][nt][1]);
            *reinterpret_cast<float2*>(&Cb[(size_t)(r + 8) * EMB + c]) =
                make_float2(acc[mt][nt][2], acc[mt][nt][3]);
        }
    }
}

// ---------------- row softmax (+ mask): S fp16 -> P fp16 --------------------
__device__ __forceinline__ float warp_max(float v)
{
#pragma unroll
    for (int o = 16; o > 0; o >>= 1) v = fmaxf(v, __shfl_xor_sync(0xffffffffu, v, o));
    return v;
}
__device__ __forceinline__ float warp_sum(float v)
{
#pragma unroll
    for (int o = 16; o > 0; o >>= 1) v += __shfl_xor_sync(0xffffffffu, v, o);
    return v;
}

__global__ void __launch_bounds__(256)
softmax_kernel(const __half* __restrict__ S, const float* __restrict__ mask,
               __half* __restrict__ P)
{
    __shared__ float red[8];
    int row = blockIdx.x;                 // b*SEQ + i
    const __half* s = S    + (size_t)row * SEQ;
    const float*  m = mask + (size_t)row * SEQ;
    __half*       p = P    + (size_t)row * SEQ;

    int base = threadIdx.x * 8;
    float v[8];
    {
        uint4 raw = *reinterpret_cast<const uint4*>(s + base);
        const __half2* h2 = reinterpret_cast<const __half2*>(&raw);
        float4 ma = *reinterpret_cast<const float4*>(m + base);
        float4 mb = *reinterpret_cast<const float4*>(m + base + 4);
        float2 f0 = __half22float2(h2[0]);
        float2 f1 = __half22float2(h2[1]);
        float2 f2 = __half22float2(h2[2]);
        float2 f3 = __half22float2(h2[3]);
        v[0] = f0.x + ma.x; v[1] = f0.y + ma.y; v[2] = f1.x + ma.z; v[3] = f1.y + ma.w;
        v[4] = f2.x + mb.x; v[5] = f2.y + mb.y; v[6] = f3.x + mb.z; v[7] = f3.y + mb.w;
    }
    float mx = v[0];
#pragma unroll
    for (int i = 1; i < 8; i++) mx = fmaxf(mx, v[i]);
    mx = warp_max(mx);
    int wid = threadIdx.x >> 5, lane = threadIdx.x & 31;
    if (lane == 0) red[wid] = mx;
    __syncthreads();
    if (wid == 0) {
        float t = (lane < 8) ? red[lane] : -1e30f;
        t = warp_max(t);
        if (lane == 0) red[0] = t;
    }
    __syncthreads();
    mx = red[0];

    float sum = 0.f;
#pragma unroll
    for (int i = 0; i < 8; i++) { v[i] = __expf(v[i] - mx); sum += v[i]; }
    sum = warp_sum(sum);
    __syncthreads();
    if (lane == 0) red[wid] = sum;
    __syncthreads();
    if (wid == 0) {
        float t = (lane < 8) ? red[lane] : 0.f;
        t = warp_sum(t);
        if (lane == 0) red[0] = t;
    }
    __syncthreads();
    float inv = 1.0f / red[0];

    __half h[8];
#pragma unroll
    for (int i = 0; i < 8; i++) h[i] = __float2half_rn(v[i] * inv);
    *reinterpret_cast<uint4*>(p + base) = *reinterpret_cast<const uint4*>(h);
}

// ---------------- launch -----------------------------------------------------
extern "C" void kernel_launch(void* const* d_in, const int* in_sizes, int n_in,
                              void* d_out, int out_size)
{
    const float* Q    = (const float*)d_in[0];
    const float* K    = (const float*)d_in[1];
    const float* V    = (const float*)d_in[2];
    const float* mask = (const float*)d_in[3];
    float* out = (float*)d_out;

    void *pQh, *pKh, *pVt, *pSh, *pP;
    cudaGetSymbolAddress(&pQh, d_Qh);
    cudaGetSymbolAddress(&pKh, d_Kh);
    cudaGetSymbolAddress(&pVt, d_Vt);
    cudaGetSymbolAddress(&pSh, d_Sh);
    cudaGetSymbolAddress(&pP,  d_P);

    cudaFuncSetAttribute(gemm_s, cudaFuncAttributeMaxDynamicSharedMemorySize, GEMM_DSMEM);
    cudaFuncSetAttribute(gemm_o, cudaFuncAttributeMaxDynamicSharedMemorySize, GEMM_DSMEM);

    const long nQK = (long)BATCH * SEQ * EMB;

    cvt_qk<<<dim3(2048, 2), 256>>>(Q, K, (__half*)pQh, (__half*)pKh, nQK);
    transpose_v<<<dim3(EMB / 32, SEQ / 32, BATCH), dim3(32, 8)>>>(V, (__half*)pVt);

    // S = (Q/32) @ K^T  (fp32 acc, fp16 out)
    gemm_s<<<dim3(SEQ / BN, SEQ / BM, BATCH), 256, GEMM_DSMEM>>>(
        (const __half*)pQh, (const __half*)pKh, (__half*)pSh);

    softmax_kernel<<<BATCH * SEQ, 256>>>((const __half*)pSh, mask, (__half*)pP);

    // O = P @ V  (fp32 acc)
    gemm_o<<<dim3(EMB / BN, SEQ / BM, BATCH), 256, GEMM_DSMEM>>>(
        (const __half*)pP, (const __half*)pVt, out);
}

// round 11
// speedup vs baseline: 1.0178x; 1.0178x over previous
#include <cuda_runtime.h>
#include <cuda_fp16.h>
#include <cuda_bf16.h>
#include <stdint.h>

// Problem shape (fixed by the reference)
#define BATCH 4
#define SEQ   2048
#define EMB   1024

// ---------------- scratch (device globals; no cudaMalloc allowed) ----------
__device__ __half d_Qh[(size_t)BATCH * SEQ * EMB];           // 16 MB (Q * 1/32)
__device__ __half d_Kh[(size_t)BATCH * SEQ * EMB];           // 16 MB
__device__ __half d_Vt[(size_t)BATCH * SEQ * EMB];           // 16 MB (V^T: [B][E][S])
__device__ __half d_Sh[(size_t)BATCH * SEQ * SEQ];           // 32 MB (scores fp16)
__device__ __half d_P [(size_t)BATCH * SEQ * SEQ];           // 32 MB (softmax probs fp16)

// ---------------- fused Q/K fp32 -> fp16 convert ----------------------------
__global__ void cvt_qk(const float* __restrict__ Q, const float* __restrict__ K,
                       __half* __restrict__ Qh, __half* __restrict__ Kh, long n)
{
    const float* in  = blockIdx.y ? K : Q;
    __half*      out = blockIdx.y ? Kh : Qh;
    float scale      = blockIdx.y ? 1.0f : 0.03125f;   // 1/sqrt(1024) folded into Q
    long i = (long)blockIdx.x * blockDim.x + threadIdx.x;
    long stride = (long)gridDim.x * blockDim.x;
    for (long idx = i * 4; idx < n; idx += stride * 4) {
        float4 v = *reinterpret_cast<const float4*>(in + idx);
        __half2 h0 = __floats2half2_rn(v.x * scale, v.y * scale);
        __half2 h1 = __floats2half2_rn(v.z * scale, v.w * scale);
        *reinterpret_cast<__half2*>(out + idx)     = h0;
        *reinterpret_cast<__half2*>(out + idx + 2) = h1;
    }
}

// ---------------- V transpose + convert: V[B][S][E] -> Vt[B][E][S] ---------
__global__ void transpose_v(const float* __restrict__ V, __half* __restrict__ Vt)
{
    __shared__ float tile[32][33];
    int b  = blockIdx.z;
    int e0 = blockIdx.x * 32;
    int j0 = blockIdx.y * 32;
    const float* Vb  = V  + (size_t)b * SEQ * EMB;
    __half*      Vtb = Vt + (size_t)b * SEQ * EMB;
    for (int r = threadIdx.y; r < 32; r += 8)
        tile[r][threadIdx.x] = Vb[(size_t)(j0 + r) * EMB + e0 + threadIdx.x];
    __syncthreads();
    for (int r = threadIdx.y; r < 32; r += 8)
        Vtb[(size_t)(e0 + r) * SEQ + j0 + threadIdx.x] = __float2half_rn(tile[threadIdx.x][r]);
}

// ---------------- helpers ---------------------------------------------------
__device__ __forceinline__ uint32_t smem_u32(const void* p)
{
    uint32_t a;
    asm("{ .reg .u64 t; cvta.to.shared.u64 t, %1; cvt.u32.u64 %0, t; }" : "=r"(a) : "l"(p));
    return a;
}

__device__ __forceinline__ void cp_async16(uint32_t dst, const void* src)
{
    asm volatile("cp.async.cg.shared.global [%0], [%1], 16;" :: "r"(dst), "l"(src));
}
#define CP_COMMIT() asm volatile("cp.async.commit_group;" ::: "memory")
#define CP_WAIT(n)  asm volatile("cp.async.wait_group %0;" :: "n"(n) : "memory")

__device__ __forceinline__ void ldsm_x4_u(uint32_t& r0, uint32_t& r1, uint32_t& r2, uint32_t& r3,
                                          uint32_t sa)
{
    asm volatile("ldmatrix.sync.aligned.m8n8.x4.shared.b16 {%0,%1,%2,%3}, [%4];"
                 : "=r"(r0), "=r"(r1), "=r"(r2), "=r"(r3) : "r"(sa));
}

__device__ __forceinline__ void mma16816(float* d, const uint32_t* a, const uint32_t* b)
{
    asm("mma.sync.aligned.m16n8k16.row.col.f32.f16.f16.f32 "
        "{%0,%1,%2,%3}, {%4,%5,%6,%7}, {%8,%9}, {%0,%1,%2,%3};"
        : "+f"(d[0]), "+f"(d[1]), "+f"(d[2]), "+f"(d[3])
        : "r"(a[0]), "r"(a[1]), "r"(a[2]), "r"(a[3]), "r"(b[0]), "r"(b[1]));
}

// ---------------- GEMM: 128x128 tile, BK=64, 3-stage cp.async ring ----------
// Row pitch 72 halfs = 144 B (16B-aligned, conflict-free ldmatrix as in R2/R9).
// 3 stages -> the load target at iter c is stage (c-1)%3, already fully read
// before the top-of-iteration barrier => ONE __syncthreads per chunk.
// __launch_bounds__(256, 2) caps regs at 128 so 2 CTAs/SM co-reside
// (2 x 110592 B smem = 221184 <= 232448 pool).
#define BM 128
#define BN 128
#define BKT 64
#define ROWB   144                       // bytes per smem row
#define ABYT   (BM * ROWB)               // 18432
#define STGB   (2 * ABYT)                // 36864 per stage (A + B)
#define GEMM_DSMEM (3 * STGB)            // 110592

// issue cp.async for chunk c of both tiles into stage s
#define CPLOAD(Ab, Bb, Kdim, c, s)                                                        \
    {                                                                                     \
        uint32_t so = (uint32_t)((s) * STGB);                                             \
        const __half* a0 = (Ab) + (size_t)(tm + (tid >> 3)) * (Kdim) + (c) * BKT + (tid & 7) * 8; \
        const __half* b0 = (Bb) + (size_t)(tn + (tid >> 3)) * (Kdim) + (c) * BKT + (tid & 7) * 8; \
        uint32_t d0 = sbase + so + (uint32_t)((tid >> 3) * ROWB + (tid & 7) * 16);        \
        _Pragma("unroll")                                                                 \
        for (int r = 0; r < 4; ++r) {                                                     \
            cp_async16(d0 + (uint32_t)(r * 32 * ROWB),        a0 + (size_t)(r * 32) * (Kdim)); \
            cp_async16(d0 + ABYT + (uint32_t)(r * 32 * ROWB), b0 + (size_t)(r * 32) * (Kdim)); \
        }                                                                                 \
    }

// 3-stage mainloop, single barrier per chunk
#define GEMM_MAINLOOP(Ab, Bb, Kdim)                                                       \
    {                                                                                     \
        const int NC = (Kdim) / BKT;                                                      \
        CPLOAD(Ab, Bb, Kdim, 0, 0) CP_COMMIT();                                           \
        CPLOAD(Ab, Bb, Kdim, 1, 1) CP_COMMIT();                                           \
        for (int c = 0; c < NC; ++c) {                                                    \
            if (c + 1 < NC) { CP_WAIT(1); } else { CP_WAIT(0); }                          \
            __syncthreads();                                                              \
            if (c + 2 < NC) { CPLOAD(Ab, Bb, Kdim, c + 2, (c + 2) % 3) CP_COMMIT(); }     \
            const uint32_t so = (uint32_t)((c % 3) * STGB);                               \
            _Pragma("unroll")                                                             \
            for (int kk = 0; kk < BKT; kk += 16) {                                        \
                uint32_t af[4][4];                                                        \
                uint32_t bf[4][2];                                                        \
                _Pragma("unroll")                                                         \
                for (int mt = 0; mt < 4; ++mt)                                            \
                    ldsm_x4_u(af[mt][0], af[mt][1], af[mt][2], af[mt][3],                 \
                              sbase + so + (uint32_t)((wm + mt * 16 + (lane & 15)) * ROWB \
                                                      + (kk + ((lane >> 4) << 3)) * 2));  \
                _Pragma("unroll")                                                         \
                for (int nb = 0; nb < 2; ++nb) {                                          \
                    uint32_t r0, r1, r2, r3;                                              \
                    ldsm_x4_u(r0, r1, r2, r3,                                             \
                              sbase + so + ABYT + (uint32_t)((wn + nb * 16 + (lane & 15)) * ROWB \
                                                      + (kk + ((lane >> 4) << 3)) * 2));  \
                    bf[nb * 2 + 0][0] = r0; bf[nb * 2 + 0][1] = r2;                       \
                    bf[nb * 2 + 1][0] = r1; bf[nb * 2 + 1][1] = r3;                       \
                }                                                                         \
                _Pragma("unroll")                                                         \
                for (int mt = 0; mt < 4; ++mt)                                            \
                    _Pragma("unroll")                                                     \
                    for (int nt = 0; nt < 4; ++nt)                                        \
                        mma16816(acc[mt][nt], af[mt], bf[nt]);                            \
            }                                                                             \
        }                                                                                 \
    }

// ---------------- GEMM1: S = (Qs) @ K^T, fp32 acc, fp16 out -----------------
__global__ void __launch_bounds__(256, 2)
gemm_s(const __half* __restrict__ A, const __half* __restrict__ B,
       __half* __restrict__ S)
{
    extern __shared__ char dsm[];
    const uint32_t sbase = smem_u32(dsm);

    const int b = blockIdx.z;
    const __half* Ab = A + (size_t)b * SEQ * EMB;
    const __half* Bb = B + (size_t)b * SEQ * EMB;
    __half*       Sb = S + (size_t)b * SEQ * SEQ;

    const int tm = blockIdx.y * BM;
    const int tn = blockIdx.x * BN;
    const int tid  = threadIdx.x;
    const int wid  = tid >> 5;
    const int lane = tid & 31;
    const int wm = (wid & 1) * 64;
    const int wn = (wid >> 1) * 32;

    float acc[4][4][4];
#pragma unroll
    for (int i = 0; i < 4; i++)
#pragma unroll
        for (int j = 0; j < 4; j++)
#pragma unroll
            for (int k = 0; k < 4; k++) acc[i][j][k] = 0.f;

    GEMM_MAINLOOP(Ab, Bb, EMB)

#pragma unroll
    for (int mt = 0; mt < 4; ++mt) {
#pragma unroll
        for (int nt = 0; nt < 4; ++nt) {
            int r = tm + wm + mt * 16 + (lane >> 2);
            int c = tn + wn + nt * 8 + ((lane & 3) << 1);
            *reinterpret_cast<__half2*>(&Sb[(size_t)r * SEQ + c]) =
                __floats2half2_rn(acc[mt][nt][0], acc[mt][nt][1]);
            *reinterpret_cast<__half2*>(&Sb[(size_t)(r + 8) * SEQ + c]) =
                __floats2half2_rn(acc[mt][nt][2], acc[mt][nt][3]);
        }
    }
}

// ---------------- GEMM2: O = P @ Vt^T, fp32 acc, fp32 out -------------------
__global__ void __launch_bounds__(256, 2)
gemm_o(const __half* __restrict__ A, const __half* __restrict__ B,
       float* __restrict__ C)
{
    extern __shared__ char dsm[];
    const uint32_t sbase = smem_u32(dsm);

    const int b = blockIdx.z;
    const __half* Ab = A + (size_t)b * SEQ * SEQ;   // P: K = SEQ
    const __half* Bb = B + (size_t)b * SEQ * EMB;   // Vt: K = SEQ
    float*        Cb = C + (size_t)b * SEQ * EMB;

    const int tm = blockIdx.y * BM;
    const int tn = blockIdx.x * BN;
    const int tid  = threadIdx.x;
    const int wid  = tid >> 5;
    const int lane = tid & 31;
    const int wm = (wid & 1) * 64;
    const int wn = (wid >> 1) * 32;

    float acc[4][4][4];
#pragma unroll
    for (int i = 0; i < 4; i++)
#pragma unroll
        for (int j = 0; j < 4; j++)
#pragma unroll
            for (int k = 0; k < 4; k++) acc[i][j][k] = 0.f;

    GEMM_MAINLOOP(Ab, Bb, SEQ)

#pragma unroll
    for (int mt = 0; mt < 4; ++mt) {
#pragma unroll
        for (int nt = 0; nt < 4; ++nt) {
            int r = tm + wm + mt * 16 + (lane >> 2);
            int c = tn + wn + nt * 8 + ((lane & 3) << 1);
            *reinterpret_cast<float2*>(&Cb[(size_t)r * EMB + c]) =
                make_float2(acc[mt][nt][0], acc[mt][nt][1]);
            *reinterpret_cast<float2*>(&Cb[(size_t)(r + 8) * EMB + c]) =
                make_float2(acc[mt][nt][2], acc[mt][nt][3]);
        }
    }
}

// ---------------- row softmax (+ mask): S fp16 -> P fp16 --------------------
__device__ __forceinline__ float warp_max(float v)
{
#pragma unroll
    for (int o = 16; o > 0; o >>= 1) v = fmaxf(v, __shfl_xor_sync(0xffffffffu, v, o));
    return v;
}
__device__ __forceinline__ float warp_sum(float v)
{
#pragma unroll
    for (int o = 16; o > 0; o >>= 1) v += __shfl_xor_sync(0xffffffffu, v, o);
    return v;
}

__global__ void __launch_bounds__(256)
softmax_kernel(const __half* __restrict__ S, const float* __restrict__ mask,
               __half* __restrict__ P)
{
    __shared__ float red[8];
    int row = blockIdx.x;                 // b*SEQ + i
    const __half* s = S    + (size_t)row * SEQ;
    const float*  m = mask + (size_t)row * SEQ;
    __half*       p = P    + (size_t)row * SEQ;

    int base = threadIdx.x * 8;
    float v[8];
    {
        uint4 raw = *reinterpret_cast<const uint4*>(s + base);
        const __half2* h2 = reinterpret_cast<const __half2*>(&raw);
        float4 ma = *reinterpret_cast<const float4*>(m + base);
        float4 mb = *reinterpret_cast<const float4*>(m + base + 4);
        float2 f0 = __half22float2(h2[0]);
        float2 f1 = __half22float2(h2[1]);
        float2 f2 = __half22float2(h2[2]);
        float2 f3 = __half22float2(h2[3]);
        v[0] = f0.x + ma.x; v[1] = f0.y + ma.y; v[2] = f1.x + ma.z; v[3] = f1.y + ma.w;
        v[4] = f2.x + mb.x; v[5] = f2.y + mb.y; v[6] = f3.x + mb.z; v[7] = f3.y + mb.w;
    }
    float mx = v[0];
#pragma unroll
    for (int i = 1; i < 8; i++) mx = fmaxf(mx, v[i]);
    mx = warp_max(mx);
    int wid = threadIdx.x >> 5, lane = threadIdx.x & 31;
    if (lane == 0) red[wid] = mx;
    __syncthreads();
    if (wid == 0) {
        float t = (lane < 8) ? red[lane] : -1e30f;
        t = warp_max(t);
        if (lane == 0) red[0] = t;
    }
    __syncthreads();
    mx = red[0];

    float sum = 0.f;
#pragma unroll
    for (int i = 0; i < 8; i++) { v[i] = __expf(v[i] - mx); sum += v[i]; }
    sum = warp_sum(sum);
    __syncthreads();
    if (lane == 0) red[wid] = sum;
    __syncthreads();
    if (wid == 0) {
        float t = (lane < 8) ? red[lane] : 0.f;
        t = warp_sum(t);
        if (lane == 0) red[0] = t;
    }
    __syncthreads();
    float inv = 1.0f / red[0];

    __half h[8];
#pragma unroll
    for (int i = 0; i < 8; i++) h[i] = __float2half_rn(v[i] * inv);
    *reinterpret_cast<uint4*>(p + base) = *reinterpret_cast<const uint4*>(h);
}

// ---------------- launch -----------------------------------------------------
extern "C" void kernel_launch(void* const* d_in, const int* in_sizes, int n_in,
                              void* d_out, int out_size)
{
    const float* Q    = (const float*)d_in[0];
    const float* K    = (const float*)d_in[1];
    const float* V    = (const float*)d_in[2];
    const float* mask = (const float*)d_in[3];
    float* out = (float*)d_out;

    void *pQh, *pKh, *pVt, *pSh, *pP;
    cudaGetSymbolAddress(&pQh, d_Qh);
    cudaGetSymbolAddress(&pKh, d_Kh);
    cudaGetSymbolAddress(&pVt, d_Vt);
    cudaGetSymbolAddress(&pSh, d_Sh);
    cudaGetSymbolAddress(&pP,  d_P);

    cudaFuncSetAttribute(gemm_s, cudaFuncAttributeMaxDynamicSharedMemorySize, GEMM_DSMEM);
    cudaFuncSetAttribute(gemm_o, cudaFuncAttributeMaxDynamicSharedMemorySize, GEMM_DSMEM);

    const long nQK = (long)BATCH * SEQ * EMB;

    cvt_qk<<<dim3(2048, 2), 256>>>(Q, K, (__half*)pQh, (__half*)pKh, nQK);
    transpose_v<<<dim3(EMB / 32, SEQ / 32, BATCH), dim3(32, 8)>>>(V, (__half*)pVt);

    // S = (Q/32) @ K^T  (fp32 acc, fp16 out)
    gemm_s<<<dim3(SEQ / BN, SEQ / BM, BATCH), 256, GEMM_DSMEM>>>(
        (const __half*)pQh, (const __half*)pKh, (__half*)pSh);

    softmax_kernel<<<BATCH * SEQ, 256>>>((const __half*)pSh, mask, (__half*)pP);

    // O = P @ V  (fp32 acc)
    gemm_o<<<dim3(EMB / BN, SEQ / BM, BATCH), 256, GEMM_DSMEM>>>(
        (const __half*)pP, (const __half*)pVt, out);
}

// round 12
// speedup vs baseline: 1.0549x; 1.0364x over previous
#include <cuda_runtime.h>
#include <cuda_fp16.h>
#include <cuda_bf16.h>
#include <stdint.h>

// Problem shape (fixed by the reference)
#define BATCH 4
#define SEQ   2048
#define EMB   1024

// ---------------- scratch (device globals; no cudaMalloc allowed) ----------
__device__ __half d_Qh[(size_t)BATCH * SEQ * EMB];           // 16 MB (Q * 1/32)
__device__ __half d_Kh[(size_t)BATCH * SEQ * EMB];           // 16 MB
__device__ __half d_Vt[(size_t)BATCH * SEQ * EMB];           // 16 MB (V^T: [B][E][S])
__device__ __half d_Sh[(size_t)BATCH * SEQ * SEQ];           // 32 MB (scores fp16)
__device__ __half d_P [(size_t)BATCH * SEQ * SEQ];           // 32 MB (softmax probs fp16)

// ---------------- fused prep: Q/K convert + V transpose, ONE launch ---------
// grid = dim3(8192, 2), block = 256
//  y==0: x in [0,4096) converts Q (scale 1/32), x in [4096,8192) converts K
//        4096 blocks x 256 thr x 8 elems = 8,388,608 = BATCH*SEQ*EMB exactly
//  y==1: x decodes (batch, e-tile, j-tile) for the 32x32 V transpose tiles
//        (1024/32)*(2048/32)*4 = 8192 tiles
__global__ void __launch_bounds__(256)
prep(const float* __restrict__ Q, const float* __restrict__ K,
     const float* __restrict__ V,
     __half* __restrict__ Qh, __half* __restrict__ Kh, __half* __restrict__ Vt)
{
    __shared__ float tile[32][33];

    if (blockIdx.y == 0) {
        const bool isK   = blockIdx.x >= 4096;
        const float* in  = isK ? K : Q;
        __half*      out = isK ? Kh : Qh;
        const float scale = isK ? 1.0f : 0.03125f;   // 1/sqrt(1024) folded into Q
        long base = ((long)(blockIdx.x & 4095) * 256 + threadIdx.x) * 8;
        float4 v0 = *reinterpret_cast<const float4*>(in + base);
        float4 v1 = *reinterpret_cast<const float4*>(in + base + 4);
        __half h[8];
        h[0] = __float2half_rn(v0.x * scale); h[1] = __float2half_rn(v0.y * scale);
        h[2] = __float2half_rn(v0.z * scale); h[3] = __float2half_rn(v0.w * scale);
        h[4] = __float2half_rn(v1.x * scale); h[5] = __float2half_rn(v1.y * scale);
        h[6] = __float2half_rn(v1.z * scale); h[7] = __float2half_rn(v1.w * scale);
        *reinterpret_cast<uint4*>(out + base) = *reinterpret_cast<const uint4*>(h);
    } else {
        const int b  = blockIdx.x >> 11;            // 2048 tiles per batch
        const int t  = blockIdx.x & 2047;
        const int e0 = (t & 31) * 32;               // 32 e-tiles
        const int j0 = (t >> 5) * 32;               // 64 j-tiles
        const int tx = threadIdx.x & 31;
        const int ty = threadIdx.x >> 5;            // 0..7
        const float* Vb  = V  + (size_t)b * SEQ * EMB;
        __half*      Vtb = Vt + (size_t)b * SEQ * EMB;
        for (int r = ty; r < 32; r += 8)
            tile[r][tx] = Vb[(size_t)(j0 + r) * EMB + e0 + tx];
        __syncthreads();
        for (int r = ty; r < 32; r += 8)
            Vtb[(size_t)(e0 + r) * SEQ + j0 + tx] = __float2half_rn(tile[tx][r]);
    }
}

// ---------------- helpers ---------------------------------------------------
__device__ __forceinline__ uint32_t smem_u32(const void* p)
{
    uint32_t a;
    asm("{ .reg .u64 t; cvta.to.shared.u64 t, %1; cvt.u32.u64 %0, t; }" : "=r"(a) : "l"(p));
    return a;
}

__device__ __forceinline__ void cp_async16(uint32_t dst, const void* src)
{
    asm volatile("cp.async.cg.shared.global [%0], [%1], 16;" :: "r"(dst), "l"(src));
}
#define CP_COMMIT() asm volatile("cp.async.commit_group;" ::: "memory")
#define CP_WAIT(n)  asm volatile("cp.async.wait_group %0;" :: "n"(n) : "memory")

__device__ __forceinline__ void ldsm_x4_u(uint32_t& r0, uint32_t& r1, uint32_t& r2, uint32_t& r3,
                                          uint32_t sa)
{
    asm volatile("ldmatrix.sync.aligned.m8n8.x4.shared.b16 {%0,%1,%2,%3}, [%4];"
                 : "=r"(r0), "=r"(r1), "=r"(r2), "=r"(r3) : "r"(sa));
}

__device__ __forceinline__ void mma16816(float* d, const uint32_t* a, const uint32_t* b)
{
    asm("mma.sync.aligned.m16n8k16.row.col.f32.f16.f16.f32 "
        "{%0,%1,%2,%3}, {%4,%5,%6,%7}, {%8,%9}, {%0,%1,%2,%3};"
        : "+f"(d[0]), "+f"(d[1]), "+f"(d[2]), "+f"(d[3])
        : "r"(a[0]), "r"(a[1]), "r"(a[2]), "r"(a[3]), "r"(b[0]), "r"(b[1]));
}

// ---------------- GEMM: 128x128 tile, BK=64, 2-stage cp.async (R9 winner) ---
// Row pitch 72 halfs = 144 B (16B-aligned, conflict-free ldmatrix).
#define BM 128
#define BN 128
#define BKT 64
#define ROWB   144                       // bytes per smem row
#define ABYT   (BM * ROWB)               // 18432
#define STGB   (2 * ABYT)                // 36864 per stage (A + B)
#define GEMM_DSMEM (2 * STGB)            // 73728

// issue cp.async for chunk c of both tiles into stage s
#define CPLOAD(Ab, Bb, Kdim, c, s)                                                        \
    {                                                                                     \
        uint32_t so = (uint32_t)((s) * STGB);                                             \
        const __half* a0 = (Ab) + (size_t)(tm + (tid >> 3)) * (Kdim) + (c) * BKT + (tid & 7) * 8; \
        const __half* b0 = (Bb) + (size_t)(tn + (tid >> 3)) * (Kdim) + (c) * BKT + (tid & 7) * 8; \
        uint32_t d0 = sbase + so + (uint32_t)((tid >> 3) * ROWB + (tid & 7) * 16);        \
        _Pragma("unroll")                                                                 \
        for (int r = 0; r < 4; ++r) {                                                     \
            cp_async16(d0 + (uint32_t)(r * 32 * ROWB),        a0 + (size_t)(r * 32) * (Kdim)); \
            cp_async16(d0 + ABYT + (uint32_t)(r * 32 * ROWB), b0 + (size_t)(r * 32) * (Kdim)); \
        }                                                                                 \
    }

// 2-stage double-buffered mainloop (exact R9 structure)
#define GEMM_MAINLOOP(Ab, Bb, Kdim)                                                       \
    {                                                                                     \
        const int NC = (Kdim) / BKT;                                                      \
        CPLOAD(Ab, Bb, Kdim, 0, 0) CP_COMMIT();                                           \
        CPLOAD(Ab, Bb, Kdim, 1, 1) CP_COMMIT();                                           \
        for (int c = 0; c < NC; ++c) {                                                    \
            if (c + 1 < NC) { CP_WAIT(1); } else { CP_WAIT(0); }                          \
            __syncthreads();                                                              \
            const uint32_t so = (uint32_t)((c & 1) * STGB);                               \
            _Pragma("unroll")                                                             \
            for (int kk = 0; kk < BKT; kk += 16) {                                        \
                uint32_t af[4][4];                                                        \
                uint32_t bf[4][2];                                                        \
                _Pragma("unroll")                                                         \
                for (int mt = 0; mt < 4; ++mt)                                            \
                    ldsm_x4_u(af[mt][0], af[mt][1], af[mt][2], af[mt][3],                 \
                              sbase + so + (uint32_t)((wm + mt * 16 + (lane & 15)) * ROWB \
                                                      + (kk + ((lane >> 4) << 3)) * 2));  \
                _Pragma("unroll")                                                         \
                for (int nb = 0; nb < 2; ++nb) {                                          \
                    uint32_t r0, r1, r2, r3;                                              \
                    ldsm_x4_u(r0, r1, r2, r3,                                             \
                              sbase + so + ABYT + (uint32_t)((wn + nb * 16 + (lane & 15)) * ROWB \
                                                      + (kk + ((lane >> 4) << 3)) * 2));  \
                    bf[nb * 2 + 0][0] = r0; bf[nb * 2 + 0][1] = r2;                       \
                    bf[nb * 2 + 1][0] = r1; bf[nb * 2 + 1][1] = r3;                       \
                }                                                                         \
                _Pragma("unroll")                                                         \
                for (int mt = 0; mt < 4; ++mt)                                            \
                    _Pragma("unroll")                                                     \
                    for (int nt = 0; nt < 4; ++nt)                                        \
                        mma16816(acc[mt][nt], af[mt], bf[nt]);                            \
            }                                                                             \
            __syncthreads();                                                              \
            if (c + 2 < NC) { CPLOAD(Ab, Bb, Kdim, c + 2, (c & 1)) CP_COMMIT(); }         \
        }                                                                                 \
    }

// ---------------- GEMM1: S = (Qs) @ K^T, fp32 acc, fp16 out -----------------
__global__ void __launch_bounds__(256, 2)
gemm_s(const __half* __restrict__ A, const __half* __restrict__ B,
       __half* __restrict__ S)
{
    extern __shared__ char dsm[];
    const uint32_t sbase = smem_u32(dsm);

    const int b = blockIdx.z;
    const __half* Ab = A + (size_t)b * SEQ * EMB;
    const __half* Bb = B + (size_t)b * SEQ * EMB;
    __half*       Sb = S + (size_t)b * SEQ * SEQ;

    const int tm = blockIdx.y * BM;
    const int tn = blockIdx.x * BN;
    const int tid  = threadIdx.x;
    const int wid  = tid >> 5;
    const int lane = tid & 31;
    const int wm = (wid & 1) * 64;
    const int wn = (wid >> 1) * 32;

    float acc[4][4][4];
#pragma unroll
    for (int i = 0; i < 4; i++)
#pragma unroll
        for (int j = 0; j < 4; j++)
#pragma unroll
            for (int k = 0; k < 4; k++) acc[i][j][k] = 0.f;

    GEMM_MAINLOOP(Ab, Bb, EMB)

#pragma unroll
    for (int mt = 0; mt < 4; ++mt) {
#pragma unroll
        for (int nt = 0; nt < 4; ++nt) {
            int r = tm + wm + mt * 16 + (lane >> 2);
            int c = tn + wn + nt * 8 + ((lane & 3) << 1);
            *reinterpret_cast<__half2*>(&Sb[(size_t)r * SEQ + c]) =
                __floats2half2_rn(acc[mt][nt][0], acc[mt][nt][1]);
            *reinterpret_cast<__half2*>(&Sb[(size_t)(r + 8) * SEQ + c]) =
                __floats2half2_rn(acc[mt][nt][2], acc[mt][nt][3]);
        }
    }
}

// ---------------- GEMM2: O = P @ Vt^T, fp32 acc, fp32 out -------------------
__global__ void __launch_bounds__(256, 2)
gemm_o(const __half* __restrict__ A, const __half* __restrict__ B,
       float* __restrict__ C)
{
    extern __shared__ char dsm[];
    const uint32_t sbase = smem_u32(dsm);

    const int b = blockIdx.z;
    const __half* Ab = A + (size_t)b * SEQ * SEQ;   // P: K = SEQ
    const __half* Bb = B + (size_t)b * SEQ * EMB;   // Vt: K = SEQ
    float*        Cb = C + (size_t)b * SEQ * EMB;

    const int tm = blockIdx.y * BM;
    const int tn = blockIdx.x * BN;
    const int tid  = threadIdx.x;
    const int wid  = tid >> 5;
    const int lane = tid & 31;
    const int wm = (wid & 1) * 64;
    const int wn = (wid >> 1) * 32;

    float acc[4][4][4];
#pragma unroll
    for (int i = 0; i < 4; i++)
#pragma unroll
        for (int j = 0; j < 4; j++)
#pragma unroll
            for (int k = 0; k < 4; k++) acc[i][j][k] = 0.f;

    GEMM_MAINLOOP(Ab, Bb, SEQ)

#pragma unroll
    for (int mt = 0; mt < 4; ++mt) {
#pragma unroll
        for (int nt = 0; nt < 4; ++nt) {
            int r = tm + wm + mt * 16 + (lane >> 2);
            int c = tn + wn + nt * 8 + ((lane & 3) << 1);
            *reinterpret_cast<float2*>(&Cb[(size_t)r * EMB + c]) =
                make_float2(acc[mt][nt][0], acc[mt][nt][1]);
            *reinterpret_cast<float2*>(&Cb[(size_t)(r + 8) * EMB + c]) =
                make_float2(acc[mt][nt][2], acc[mt][nt][3]);
        }
    }
}

// ---------------- row softmax (+ mask): S fp16 -> P fp16 --------------------
__device__ __forceinline__ float warp_max(float v)
{
#pragma unroll
    for (int o = 16; o > 0; o >>= 1) v = fmaxf(v, __shfl_xor_sync(0xffffffffu, v, o));
    return v;
}
__device__ __forceinline__ float warp_sum(float v)
{
#pragma unroll
    for (int o = 16; o > 0; o >>= 1) v += __shfl_xor_sync(0xffffffffu, v, o);
    return v;
}

__global__ void __launch_bounds__(256)
softmax_kernel(const __half* __restrict__ S, const float* __restrict__ mask,
               __half* __restrict__ P)
{
    __shared__ float red[8];
    int row = blockIdx.x;                 // b*SEQ + i
    const __half* s = S    + (size_t)row * SEQ;
    const float*  m = mask + (size_t)row * SEQ;
    __half*       p = P    + (size_t)row * SEQ;

    int base = threadIdx.x * 8;
    float v[8];
    {
        uint4 raw = *reinterpret_cast<const uint4*>(s + base);
        const __half2* h2 = reinterpret_cast<const __half2*>(&raw);
        float4 ma = *reinterpret_cast<const float4*>(m + base);
        float4 mb = *reinterpret_cast<const float4*>(m + base + 4);
        float2 f0 = __half22float2(h2[0]);
        float2 f1 = __half22float2(h2[1]);
        float2 f2 = __half22float2(h2[2]);
        float2 f3 = __half22float2(h2[3]);
        v[0] = f0.x + ma.x; v[1] = f0.y + ma.y; v[2] = f1.x + ma.z; v[3] = f1.y + ma.w;
        v[4] = f2.x + mb.x; v[5] = f2.y + mb.y; v[6] = f3.x + mb.z; v[7] = f3.y + mb.w;
    }
    float mx = v[0];
#pragma unroll
    for (int i = 1; i < 8; i++) mx = fmaxf(mx, v[i]);
    mx = warp_max(mx);
    int wid = threadIdx.x >> 5, lane = threadIdx.x & 31;
    if (lane == 0) red[wid] = mx;
    __syncthreads();
    if (wid == 0) {
        float t = (lane < 8) ? red[lane] : -1e30f;
        t = warp_max(t);
        if (lane == 0) red[0] = t;
    }
    __syncthreads();
    mx = red[0];

    float sum = 0.f;
#pragma unroll
    for (int i = 0; i < 8; i++) { v[i] = __expf(v[i] - mx); sum += v[i]; }
    sum = warp_sum(sum);
    __syncthreads();
    if (lane == 0) red[wid] = sum;
    __syncthreads();
    if (wid == 0) {
        float t = (lane < 8) ? red[lane] : 0.f;
        t = warp_sum(t);
        if (lane == 0) red[0] = t;
    }
    __syncthreads();
    float inv = 1.0f / red[0];

    __half h[8];
#pragma unroll
    for (int i = 0; i < 8; i++) h[i] = __float2half_rn(v[i] * inv);
    *reinterpret_cast<uint4*>(p + base) = *reinterpret_cast<const uint4*>(h);
}

// ---------------- launch -----------------------------------------------------
extern "C" void kernel_launch(void* const* d_in, const int* in_sizes, int n_in,
                              void* d_out, int out_size)
{
    const float* Q    = (const float*)d_in[0];
    const float* K    = (const float*)d_in[1];
    const float* V    = (const float*)d_in[2];
    const float* mask = (const float*)d_in[3];
    float* out = (float*)d_out;

    void *pQh, *pKh, *pVt, *pSh, *pP;
    cudaGetSymbolAddress(&pQh, d_Qh);
    cudaGetSymbolAddress(&pKh, d_Kh);
    cudaGetSymbolAddress(&pVt, d_Vt);
    cudaGetSymbolAddress(&pSh, d_Sh);
    cudaGetSymbolAddress(&pP,  d_P);

    cudaFuncSetAttribute(gemm_s, cudaFuncAttributeMaxDynamicSharedMemorySize, GEMM_DSMEM);
    cudaFuncSetAttribute(gemm_o, cudaFuncAttributeMaxDynamicSharedMemorySize, GEMM_DSMEM);

    // fused Q/K convert + V transpose (single launch)
    prep<<<dim3(8192, 2), 256>>>(Q, K, V,
                                 (__half*)pQh, (__half*)pKh, (__half*)pVt);

    // S = (Q/32) @ K^T  (fp32 acc, fp16 out)
    gemm_s<<<dim3(SEQ / BN, SEQ / BM, BATCH), 256, GEMM_DSMEM>>>(
        (const __half*)pQh, (const __half*)pKh, (__half*)pSh);

    softmax_kernel<<<BATCH * SEQ, 256>>>((const __half*)pSh, mask, (__half*)pP);

    // O = P @ V  (fp32 acc)
    gemm_o<<<dim3(EMB / BN, SEQ / BM, BATCH), 256, GEMM_DSMEM>>>(
        (const __half*)pP, (const __half*)pVt, out);
}